// round 2
// baseline (speedup 1.0000x reference)
#include <cuda_runtime.h>

// Problem constants (match reference: shape_data=[8,32,32], n_b=2, pow=1, dt=dx=dy=1)
#define NN 1024   // nodes per grid (32*32)
#define NT 8
#define NX 32
#define NY 32

// 9-point stencil offsets, order: C, E, W, N, S, NE, SW, (+1,-1), (-1,+1)
__device__ __constant__ int OFF_DI[9] = {0, 0, 0, 1, -1, 1, -1, 1, -1};
__device__ __constant__ int OFF_DJ[9] = {0, 1, -1, 0, 0, 1, -1, -1, 1};
// (di+1)*3+(dj+1) -> stencil index o
__device__ __constant__ int OMAP[9] = {6, 4, 8, 2, 0, 1, 7, 3, 5};
// inverse offset: o -> o' with off[o'] = -off[o]
__device__ __constant__ int OINV[9] = {0, 2, 1, 4, 3, 6, 5, 8, 7};

// One CTA per output matrix row.
// grid: x = j (row node, 0..1023), y = t (0..7), z = b*3 + s  (s: 0=D,1=lower,2=upper)
__global__ __launch_bounds__(256) void spde_prior_kernel(
    const float* __restrict__ kappa,  // [n_b,1,NN,NT]
    const float* __restrict__ mm,     // [n_b,2,NN,NT]
    const float* __restrict__ HH,     // [n_b,2,2,NN,NT]
    const float* __restrict__ tau,    // [n_b,1,NN,NT]
    float* __restrict__ out)          // [n_b,3,NT,NN,NN]
{
    const int j   = blockIdx.x;
    const int t   = blockIdx.y;
    const int zs  = blockIdx.z;
    const int b   = zs / 3;
    const int s   = zs % 3;
    const int tid = threadIdx.x;

    __shared__ float e[9][9];   // e[i_neighbor][o] = M[node_i, node_i + off[o]]
    __shared__ float wv[9];     // w at each neighbor node
    __shared__ alignas(16) float row[NN];

    // zero shared row (256 threads * float4 = 1024 floats)
    ((float4*)row)[tid] = make_float4(0.f, 0.f, 0.f, 0.f);

    const int ii = j >> 5;
    const int jj = j & 31;
    const int tt = (s == 2) ? (t + 1) : t;   // upper blocks use time t+1 coefficients

    // Stage stencil-entry values of M (= I + A) for the 9 neighbor nodes of j at time tt.
    if (tid < 9 && tt < NT) {
        const int di = OFF_DI[tid], dj = OFF_DJ[tid];
        const int ni = ii + di, nj = jj + dj;
        const bool v = (ni >= 0) && (ni < NY) && (nj >= 0) && (nj < NX);
        float w = 0.f;
        float c0 = 0.f, cE = 0.f, cW = 0.f, cN = 0.f, cS = 0.f, cx = 0.f;
        if (v) {
            const int n     = ni * NX + nj;
            const int kbase = (b * NN + n) * NT + tt;
            const float ka  = __ldg(&kappa[kbase]);
            const float ta  = __ldg(&tau[kbase]);
            const float m1  = __ldg(&mm[(b * 2 * NN + n) * NT + tt]);
            const float m2  = __ldg(&mm[((b * 2 + 1) * NN + n) * NT + tt]);
            const float h11 = __ldg(&HH[(b * 4 * NN + n) * NT + tt]);
            const float h12 = __ldg(&HH[((b * 4 + 1) * NN + n) * NT + tt]);
            const float h22 = __ldg(&HH[((b * 4 + 3) * NN + n) * NT + tt]);
            w  = 1.f / (ta * ta);                       // dt/tau^2, dt=1
            c0 = 1.f + ka * ka + 2.f * (h11 + h22);     // M center = 1 + A center
            cE = -h11 + 0.5f * m1;
            cW = -h11 - 0.5f * m1;
            cN = -h22 + 0.5f * m2;
            cS = -h22 - 0.5f * m2;
            cx = 0.5f * h12;
        }
        const float vals[9] = {c0, cE, cW, cN, cS, -cx, -cx, cx, cx};
        #pragma unroll
        for (int o = 0; o < 9; o++) {
            // entry is zero if its COLUMN (node + off[o]) is off-grid (Dirichlet)
            const int ci = ni + OFF_DI[o], cj = nj + OFF_DJ[o];
            const bool cv = v && (ci >= 0) && (ci < NY) && (cj >= 0) && (cj < NX);
            e[tid][o] = cv ? vals[o] : 0.f;
        }
        wv[tid] = w;  // 0 for off-grid neighbor -> its terms vanish
    }
    __syncthreads();

    if (s == 0) {
        // D[j,k] = sum_i w_i * M[i,j] * M[i,k]  (+ w_{t+1}[j] at k=j, t<NT-1)
        if (tid < 25) {
            const int ddi = tid / 5 - 2, ddj = tid % 5 - 2;
            const int ki = ii + ddi, kj = jj + ddj;
            if (ki >= 0 && ki < NY && kj >= 0 && kj < NX) {
                float sum = 0.f;
                #pragma unroll
                for (int o = 0; o < 9; o++) {
                    const int d2i = ddi - OFF_DI[o], d2j = ddj - OFF_DJ[o];
                    if (d2i < -1 || d2i > 1 || d2j < -1 || d2j > 1) continue;
                    const int o2 = OMAP[(d2i + 1) * 3 + (d2j + 1)];
                    sum += wv[o] * e[o][OINV[o]] * e[o][o2];
                }
                if (ddi == 0 && ddj == 0 && t < NT - 1) {
                    const float tn = __ldg(&tau[(b * NN + j) * NT + t + 1]);
                    sum += 1.f / (tn * tn);
                }
                row[ki * NX + kj] = sum;
            }
        }
    } else if (s == 1) {
        // lower[t][j,k] = -w_t[k] * M_t[k,j],  t >= 1 (t==0 block is zero)
        if (t > 0 && tid < 9) {
            const int ki = ii + OFF_DI[tid], kj = jj + OFF_DJ[tid];
            if (ki >= 0 && ki < NY && kj >= 0 && kj < NX) {
                row[ki * NX + kj] = -wv[tid] * e[tid][OINV[tid]];
            }
        }
    } else {
        // upper[t][j,k] = -w_{t+1}[j] * M_{t+1}[j,k],  t <= NT-2 (t==NT-1 is zero)
        if (t < NT - 1 && tid < 9) {
            const int ki = ii + OFF_DI[tid], kj = jj + OFF_DJ[tid];
            if (ki >= 0 && ki < NY && kj >= 0 && kj < NX) {
                row[ki * NX + kj] = -wv[0] * e[0][tid];
            }
        }
    }
    __syncthreads();

    // coalesced row write: 256 threads * float4
    float4* o4 = (float4*)(out + (((size_t)(b * 3 + s) * NT + t) * NN + (size_t)j) * NN);
    o4[tid] = ((float4*)row)[tid];
}

extern "C" void kernel_launch(void* const* d_in, const int* in_sizes, int n_in,
                              void* d_out, int out_size) {
    const float* kappa = (const float*)d_in[0];
    const float* mm    = (const float*)d_in[1];
    const float* HH    = (const float*)d_in[2];
    const float* tau   = (const float*)d_in[3];
    float* out         = (float*)d_out;

    const int n_b = in_sizes[0] / (NN * NT);   // kappa is [n_b,1,NN,NT]
    dim3 grid(NN, NT, n_b * 3);
    spde_prior_kernel<<<grid, 256>>>(kappa, mm, HH, tau, out);
}

// round 3
// speedup vs baseline: 1.3786x; 1.3786x over previous
#include <cuda_runtime.h>

// Problem constants (reference: shape_data=[8,32,32], pow=1, dt=dx=dy=1)
#define NN 1024
#define NT 8
#define NX 32
#define NY 32

// 9-point stencil offsets, order: C, E, W, N, S, NE, SW, (+1,-1), (-1,+1)
__device__ __constant__ int OFF_DI[9] = {0, 0, 0, 1, -1, 1, -1, 1, -1};
__device__ __constant__ int OFF_DJ[9] = {0, 1, -1, 0, 0, 1, -1, -1, 1};
// (di+1)*3+(dj+1) -> stencil index o
__device__ __constant__ int OMAP[9] = {6, 4, 8, 2, 0, 1, 7, 3, 5};
// inverse offset: o -> o' with off[o'] = -off[o]
__device__ __constant__ int OINV[9] = {0, 2, 1, 4, 3, 6, 5, 8, 7};

// One CTA per (b, t, j): writes the j-th row of D, lower, upper blocks (3 x 4KB).
// grid: x = j (0..1023), y = t (0..7), z = b
__global__ __launch_bounds__(256) void spde_prior_kernel(
    const float* __restrict__ kappa,  // [n_b,1,NN,NT]
    const float* __restrict__ mm,     // [n_b,2,NN,NT]
    const float* __restrict__ HH,     // [n_b,2,2,NN,NT]
    const float* __restrict__ tau,    // [n_b,1,NN,NT]
    float* __restrict__ out)          // [n_b,3,NT,NN,NN]
{
    const int j   = blockIdx.x;
    const int t   = blockIdx.y;
    const int b   = blockIdx.z;
    const int tid = threadIdx.x;

    // coefficient tables for time t (slot 0) and t+1 (slot 1)
    __shared__ float e[2][9][9];   // e[ts][i][o] = M[node_i, node_i + off[o]]
    __shared__ float wv[2][9];     // w = 1/tau^2 at each neighbor node

    const int ii = j >> 5;
    const int jj = j & 31;

    // Stage: threads 0..8 -> time t, threads 9..17 -> time t+1
    if (tid < 18) {
        const int ts = tid / 9;        // 0: time t, 1: time t+1
        const int o9 = tid % 9;
        const int tt = t + ts;
        const int di = OFF_DI[o9], dj = OFF_DJ[o9];
        const int ni = ii + di, nj = jj + dj;
        const bool v = (tt < NT) && (ni >= 0) && (ni < NY) && (nj >= 0) && (nj < NX);
        float w = 0.f;
        float c0 = 0.f, cE = 0.f, cW = 0.f, cN = 0.f, cS = 0.f, cx = 0.f;
        if (v) {
            const int n     = ni * NX + nj;
            const int kbase = (b * NN + n) * NT + tt;
            const float ka  = __ldg(&kappa[kbase]);
            const float ta  = __ldg(&tau[kbase]);
            const float m1  = __ldg(&mm[(b * 2 * NN + n) * NT + tt]);
            const float m2  = __ldg(&mm[((b * 2 + 1) * NN + n) * NT + tt]);
            const float h11 = __ldg(&HH[(b * 4 * NN + n) * NT + tt]);
            const float h12 = __ldg(&HH[((b * 4 + 1) * NN + n) * NT + tt]);
            const float h22 = __ldg(&HH[((b * 4 + 3) * NN + n) * NT + tt]);
            w  = 1.f / (ta * ta);                    // dt/tau^2, dt=1
            c0 = 1.f + ka * ka + 2.f * (h11 + h22);  // M center = 1 + A center
            cE = -h11 + 0.5f * m1;
            cW = -h11 - 0.5f * m1;
            cN = -h22 + 0.5f * m2;
            cS = -h22 - 0.5f * m2;
            cx = 0.5f * h12;
        }
        const float vals[9] = {c0, cE, cW, cN, cS, -cx, -cx, cx, cx};
        #pragma unroll
        for (int o = 0; o < 9; o++) {
            // entry is zero if its COLUMN node is off-grid (Dirichlet)
            const int ci = ni + OFF_DI[o], cj = nj + OFF_DJ[o];
            const bool cv = v && (ci >= 0) && (ci < NY) && (cj >= 0) && (cj < NX);
            e[ts][o9][o] = cv ? vals[o] : 0.f;
        }
        wv[ts][o9] = w;   // 0 for off-grid neighbor -> its terms vanish
    }
    __syncthreads();

    // Each thread owns 4 consecutive columns k = 4*tid .. 4*tid+3 (same grid row ki).
    const int c0  = tid << 2;
    const int ki  = c0 >> 5;
    const int kjb = c0 & 31;
    const int ddi = ki - ii;

    float vD[4] = {0.f, 0.f, 0.f, 0.f};
    float vL[4] = {0.f, 0.f, 0.f, 0.f};
    float vU[4] = {0.f, 0.f, 0.f, 0.f};

    if (ddi >= -2 && ddi <= 2) {
        #pragma unroll
        for (int c = 0; c < 4; c++) {
            const int ddj = kjb + c - jj;
            if (ddj < -2 || ddj > 2) continue;
            // D[j,k] = sum_i w_i * M[i,j] * M[i,k]
            float sum = 0.f;
            #pragma unroll
            for (int o = 0; o < 9; o++) {
                const int d2i = ddi - OFF_DI[o], d2j = ddj - OFF_DJ[o];
                if (d2i < -1 || d2i > 1 || d2j < -1 || d2j > 1) continue;
                const int o2 = OMAP[(d2i + 1) * 3 + (d2j + 1)];
                sum += wv[0][o] * e[0][o][OINV[o]] * e[0][o][o2];
            }
            if (ddi == 0 && ddj == 0 && t < NT - 1)
                sum += wv[1][0];                     // + w_{t+1}[j] on diagonal
            vD[c] = sum;

            if (ddi >= -1 && ddi <= 1 && ddj >= -1 && ddj <= 1) {
                const int o = OMAP[(ddi + 1) * 3 + (ddj + 1)];
                // lower[t][j,k] = -w_t[k] * M_t[k,j]   (t==0 block is zero)
                if (t > 0)       vL[c] = -wv[0][o] * e[0][o][OINV[o]];
                // upper[t][j,k] = -w_{t+1}[j] * M_{t+1}[j,k]  (t==NT-1 block is zero)
                if (t < NT - 1)  vU[c] = -wv[1][0] * e[1][0][o];
            }
        }
    }

    // coalesced float4 stores, 3 rows (D, lower, upper)
    const size_t blk = (size_t)NT * NN * NN;
    float* base = out + ((size_t)b * 3 * NT + t) * (size_t)NN * NN + (size_t)j * NN;
    ((float4*)base)[tid]                 = make_float4(vD[0], vD[1], vD[2], vD[3]);
    ((float4*)(base + blk))[tid]         = make_float4(vL[0], vL[1], vL[2], vL[3]);
    ((float4*)(base + 2 * blk))[tid]     = make_float4(vU[0], vU[1], vU[2], vU[3]);
}

extern "C" void kernel_launch(void* const* d_in, const int* in_sizes, int n_in,
                              void* d_out, int out_size) {
    const float* kappa = (const float*)d_in[0];
    const float* mm    = (const float*)d_in[1];
    const float* HH    = (const float*)d_in[2];
    const float* tau   = (const float*)d_in[3];
    float* out         = (float*)d_out;

    const int n_b = in_sizes[0] / (NN * NT);   // kappa is [n_b,1,NN,NT]
    dim3 grid(NN, NT, n_b);
    spde_prior_kernel<<<grid, 256>>>(kappa, mm, HH, tau, out);
}